// round 1
// baseline (speedup 1.0000x reference)
#include <cuda_runtime.h>

#define Bb 8
#define Tt 2048
#define Cc 4096
#define Uu 200
#define NEGF (-1e30f)

// Scratch (no cudaMalloc allowed): lpt [B,T,U] fp32 = 13.1 MB, per-batch finals, dtype flag.
__device__ float g_lpt[Bb * Tt * Uu];
__device__ float g_final[Bb];
__device__ int   g_is64;

// ---------------------------------------------------------------------------
// Kernel 0: detect whether targets are int64 (odd 32-bit words all zero) or int32.
// Values are in [0, 4096), so for int64 little-endian the high words are 0;
// for int32 the odd slots are independent random targets (P(all zero) ~ 0).
// ---------------------------------------------------------------------------
__global__ void detect_kernel(const int* __restrict__ t32) {
    int all0 = 1;
    #pragma unroll
    for (int i = 1; i < 64; i += 2) all0 &= (t32[i] == 0);
    g_is64 = all0;
}

// ---------------------------------------------------------------------------
// Kernel 1: for each row r = b*T + t compute lse = logsumexp(inputs[r,:]) and
// g_lpt[r*U + u] = inputs[r, targets[b,u]] - lse.
// One block (256 threads) per row; row (16 KB) loaded once via float4.
// ---------------------------------------------------------------------------
__global__ __launch_bounds__(256) void lpt_kernel(const float* __restrict__ inp,
                                                  const int* __restrict__ t32) {
    const int r = blockIdx.x;          // 0 .. B*T-1
    const int b = r >> 11;             // T = 2048
    const int tid = threadIdx.x;
    const float* __restrict__ row = inp + (size_t)r * Cc;
    const float4* __restrict__ row4 = (const float4*)row;

    // 16 floats per thread (4 x float4), kept in registers
    float4 v[4];
    float m = NEGF;
    #pragma unroll
    for (int i = 0; i < 4; i++) {
        v[i] = row4[tid + 256 * i];
        m = fmaxf(m, fmaxf(fmaxf(v[i].x, v[i].y), fmaxf(v[i].z, v[i].w)));
    }

    __shared__ float s_red[32];
    // block max
    #pragma unroll
    for (int off = 16; off; off >>= 1) m = fmaxf(m, __shfl_xor_sync(0xFFFFFFFFu, m, off));
    if ((tid & 31) == 0) s_red[tid >> 5] = m;
    __syncthreads();
    if (tid < 32) {
        float mm = (tid < 8) ? s_red[tid] : NEGF;
        #pragma unroll
        for (int off = 4; off; off >>= 1) mm = fmaxf(mm, __shfl_xor_sync(0xFFFFFFFFu, mm, off));
        if (tid == 0) s_red[0] = mm;
    }
    __syncthreads();
    m = s_red[0];

    // sum of exps
    float s = 0.f;
    #pragma unroll
    for (int i = 0; i < 4; i++) {
        s += __expf(v[i].x - m) + __expf(v[i].y - m) + __expf(v[i].z - m) + __expf(v[i].w - m);
    }
    #pragma unroll
    for (int off = 16; off; off >>= 1) s += __shfl_xor_sync(0xFFFFFFFFu, s, off);
    __shared__ float s_sum[8];
    if ((tid & 31) == 0) s_sum[tid >> 5] = s;
    __syncthreads();
    if (tid == 0) {
        float tot = 0.f;
        #pragma unroll
        for (int i = 0; i < 8; i++) tot += s_sum[i];
        s_red[0] = m + __logf(tot);   // lse
    }
    __syncthreads();
    const float lse = s_red[0];

    // gather the 200 target columns (row is hot in L1)
    if (tid < Uu) {
        const int base = b * Uu + tid;
        const int c = g_is64 ? t32[2 * base] : t32[base];
        g_lpt[(size_t)r * Uu + tid] = row[c] - lse;
    }
}

// ---------------------------------------------------------------------------
// Kernel 2: alpha recursion, one block per batch.
// alpha[u] stays in a register; the u-1 neighbor crosses threads via
// double-buffered smem with a single barrier per step. lpt[t+1] prefetched.
// ---------------------------------------------------------------------------
__global__ __launch_bounds__(256) void alpha_kernel() {
    const int b = blockIdx.x;
    const int u = threadIdx.x;          // 0..255 (u >= 200 are padding lanes)
    const float* __restrict__ L = g_lpt + (size_t)b * Tt * Uu;

    __shared__ float buf[2][256];

    float a = (u == 0) ? L[0] : NEGF;
    float nxt = (u < Uu) ? L[Uu + u] : 0.f;   // lpt[t=1][u]

    for (int t = 1; t < Tt; t++) {
        const float cur = nxt;
        if (t + 1 < Tt && u < Uu) nxt = L[(t + 1) * Uu + u];   // prefetch before barrier

        float* bf = buf[t & 1];
        bf[u] = a;
        __syncthreads();
        const float left = (u == 0) ? NEGF : bf[u - 1];

        // logaddexp(a, left)
        const float mx = fmaxf(a, left);
        const float d  = fabsf(a - left);
        a = cur + mx + __logf(1.f + __expf(-d));
    }

    if (u == Uu - 1) g_final[b] = a;
}

// ---------------------------------------------------------------------------
// Kernel 3: loss = mean_b(-alpha_final[b])
// ---------------------------------------------------------------------------
__global__ void finish_kernel(float* __restrict__ out) {
    float s = 0.f;
    #pragma unroll
    for (int i = 0; i < Bb; i++) s += g_final[i];
    out[0] = -s * (1.0f / Bb);
}

extern "C" void kernel_launch(void* const* d_in, const int* in_sizes, int n_in,
                              void* d_out, int out_size) {
    // inputs: B*T*C floats; targets: B*U ints (32- or 64-bit). Swap-proof ordering.
    int ii = 0, ti = 1;
    if (n_in >= 2 && in_sizes[0] < in_sizes[1]) { ii = 1; ti = 0; }
    const float* inp = (const float*)d_in[ii];
    const int*   t32 = (const int*)d_in[ti];
    float* out = (float*)d_out;

    detect_kernel<<<1, 1>>>(t32);
    lpt_kernel<<<Bb * Tt, 256>>>(inp, t32);
    alpha_kernel<<<Bb, 256>>>();
    finish_kernel<<<1, 1>>>(out);
}

// round 2
// speedup vs baseline: 2.0941x; 2.0941x over previous
#include <cuda_runtime.h>

#define Bb 8
#define Tt 2048
#define Cc 4096
#define Uu 200
#define Kk 8                       // u-values per lane
#define NLANE 25                   // 25 * 8 = 200
#define NEGF (-1e30f)
#define LOG2E 1.4426950408889634f
#define LN2   0.6931471805599453f

// Scratch (no cudaMalloc allowed): lpt2 [B,T,U] fp32 (log2-scaled) = 13.1 MB.
__device__ float g_lpt[Bb * Tt * Uu];
__device__ float g_final[Bb];
__device__ int   g_is64;

__device__ __forceinline__ float ex2f(float x) {
    float r; asm("ex2.approx.f32 %0, %1;" : "=f"(r) : "f"(x)); return r;
}
__device__ __forceinline__ float lg2f(float x) {
    float r; asm("lg2.approx.f32 %0, %1;" : "=f"(r) : "f"(x)); return r;
}

// ---------------------------------------------------------------------------
// Kernel 0: detect int64 vs int32 targets (odd 32-bit words all zero => int64).
// ---------------------------------------------------------------------------
__global__ void detect_kernel(const int* __restrict__ t32) {
    int all0 = 1;
    #pragma unroll
    for (int i = 1; i < 64; i += 2) all0 &= (t32[i] == 0);
    g_is64 = all0;
}

// ---------------------------------------------------------------------------
// Kernel 1: per row r=b*T+t: lse = logsumexp(inputs[r,:]);
// g_lpt[r*U+u] = (inputs[r,targets[b,u]] - lse) * LOG2E   (log2 domain)
// ---------------------------------------------------------------------------
__global__ __launch_bounds__(256) void lpt_kernel(const float* __restrict__ inp,
                                                  const int* __restrict__ t32) {
    const int r = blockIdx.x;
    const int b = r >> 11;             // T = 2048
    const int tid = threadIdx.x;
    const float* __restrict__ row = inp + (size_t)r * Cc;
    const float4* __restrict__ row4 = (const float4*)row;

    float4 v[4];
    float m = NEGF;
    #pragma unroll
    for (int i = 0; i < 4; i++) {
        v[i] = row4[tid + 256 * i];
        m = fmaxf(m, fmaxf(fmaxf(v[i].x, v[i].y), fmaxf(v[i].z, v[i].w)));
    }

    __shared__ float s_red[32];
    #pragma unroll
    for (int off = 16; off; off >>= 1) m = fmaxf(m, __shfl_xor_sync(0xFFFFFFFFu, m, off));
    if ((tid & 31) == 0) s_red[tid >> 5] = m;
    __syncthreads();
    if (tid < 32) {
        float mm = (tid < 8) ? s_red[tid] : NEGF;
        #pragma unroll
        for (int off = 4; off; off >>= 1) mm = fmaxf(mm, __shfl_xor_sync(0xFFFFFFFFu, mm, off));
        if (tid == 0) s_red[0] = mm;
    }
    __syncthreads();
    m = s_red[0];

    float s = 0.f;
    #pragma unroll
    for (int i = 0; i < 4; i++) {
        s += __expf(v[i].x - m) + __expf(v[i].y - m) + __expf(v[i].z - m) + __expf(v[i].w - m);
    }
    #pragma unroll
    for (int off = 16; off; off >>= 1) s += __shfl_xor_sync(0xFFFFFFFFu, s, off);
    __shared__ float s_sum[8];
    if ((tid & 31) == 0) s_sum[tid >> 5] = s;
    __syncthreads();
    if (tid == 0) {
        float tot = 0.f;
        #pragma unroll
        for (int i = 0; i < 8; i++) tot += s_sum[i];
        s_red[0] = m + __logf(tot);   // lse (natural log domain)
    }
    __syncthreads();
    const float lse = s_red[0];

    if (tid < Uu) {
        const int base = b * Uu + tid;
        const int c = g_is64 ? t32[2 * base] : t32[base];
        g_lpt[(size_t)r * Uu + tid] = (row[c] - lse) * LOG2E;
    }
}

// ---------------------------------------------------------------------------
// Kernel 2: alpha recursion in log2 domain. One WARP per batch, no barriers.
// Lane j owns u = j*8 .. j*8+7 in registers; left-neighbor crosses lanes via
// one shfl_up per step. lpt tiles staged through a depth-4 register ring.
// ---------------------------------------------------------------------------
__global__ __launch_bounds__(32) void alpha_kernel() {
    const int b = blockIdx.x;
    const int lane = threadIdx.x;
    const int lc = (lane < NLANE) ? lane : (NLANE - 1);    // clamp idle lanes
    const float* __restrict__ Lb = g_lpt + (size_t)b * Tt * Uu + lc * Kk;

    // alpha registers (log2 domain): a[k] = alpha2[u = lc*8 + k]
    float a[Kk];
    #pragma unroll
    for (int k = 0; k < Kk; k++) a[k] = NEGF;
    if (lane == 0) a[0] = Lb[0];                           // lpt2[t=0][u=0]

    // depth-4 prefetch ring of lpt2[t][lc*8 .. lc*8+7]
    float4 pA[4], pB[4];
    #pragma unroll
    for (int i = 0; i < 4; i++) {
        const float4* p = (const float4*)(Lb + (size_t)(1 + i) * Uu);
        pA[i] = p[0]; pB[i] = p[1];
    }

    #pragma unroll 4
    for (int t = 1; t < Tt; t++) {
        const int slot = (t - 1) & 3;
        const float4 cA = pA[slot];
        const float4 cB = pB[slot];

        // prefetch t+4 (clamped; redundant tail loads are harmless)
        {
            int tp = t + 4; tp = (tp < Tt) ? tp : (Tt - 1);
            const float4* p = (const float4*)(Lb + (size_t)tp * Uu);
            pA[slot] = p[0]; pB[slot] = p[1];
        }

        // neighbor's rightmost alpha from previous step
        float left_in = __shfl_up_sync(0xFFFFFFFFu, a[Kk - 1], 1);
        if (lane == 0) left_in = NEGF;

        float c[Kk] = {cA.x, cA.y, cA.z, cA.w, cB.x, cB.y, cB.z, cB.w};
        float lft[Kk];
        lft[0] = left_in;
        #pragma unroll
        for (int k = 1; k < Kk; k++) lft[k] = a[k - 1];

        // all 8 logaddexp2's are independent (depend only on old a[])
        #pragma unroll
        for (int k = 0; k < Kk; k++) {
            const float mx = fmaxf(a[k], lft[k]);
            const float d  = fabsf(a[k] - lft[k]);
            const float e  = ex2f(-d);          // 2^-d
            const float p  = lg2f(1.0f + e);    // log2(1 + 2^-d)
            a[k] = (c[k] + mx) + p;
        }
    }

    if (lane == NLANE - 1) g_final[b] = a[Kk - 1];         // u = 199, log2 units
}

// ---------------------------------------------------------------------------
// Kernel 3: loss = mean_b(-alpha_final[b]) converted back to natural log.
// ---------------------------------------------------------------------------
__global__ void finish_kernel(float* __restrict__ out) {
    float s = 0.f;
    #pragma unroll
    for (int i = 0; i < Bb; i++) s += g_final[i];
    out[0] = -s * (LN2 / Bb);
}

extern "C" void kernel_launch(void* const* d_in, const int* in_sizes, int n_in,
                              void* d_out, int out_size) {
    int ii = 0, ti = 1;
    if (n_in >= 2 && in_sizes[0] < in_sizes[1]) { ii = 1; ti = 0; }
    const float* inp = (const float*)d_in[ii];
    const int*   t32 = (const int*)d_in[ti];
    float* out = (float*)d_out;

    detect_kernel<<<1, 1>>>(t32);
    lpt_kernel<<<Bb * Tt, 256>>>(inp, t32);
    alpha_kernel<<<Bb, 32>>>();
    finish_kernel<<<1, 1>>>(out);
}